// round 12
// baseline (speedup 1.0000x reference)
#include <cuda_runtime.h>
#include <cstdint>

// Q = L @ L^T, L lower-triangular 3x3 from packed [a,b,c,d,e,f]:
//   Q00=a*a  Q01=a*b      Q02=a*d
//   Q10=a*b  Q11=b*b+c*c  Q12=b*d+c*e
//   Q20=a*d  Q21=b*d+c*e  Q22=d*d+e*e+f*f
//
// 4-tile pipeline: per-lane cp.async.cg reads (many small concurrent ops —
// R11 showed bulk reads regress), ping-pong 2x6KB input buffers, and ONE
// 36KB contiguous cp.async.bulk store per block (few large sequential write
// bursts — the R9/R10 winning lever, scaled again), with an L2 evict_first
// cache-policy hint so dirty output lines drain promptly.
// Warp-autonomous: each warp's 64-row slice per tile is self-contained, so
// input-buffer reuse needs only that warp's own wait_group + __syncwarp.

#define TPB 128
#define ROWS_PB 256
#define TILES_PB 4
#define TILE_IN_FLOATS (ROWS_PB * 6)     // 1536 floats = 6144 B
#define TILE_OUT_FLOATS (ROWS_PB * 9)    // 2304 floats = 9216 B
#define W_IN_F4 96                       // per-warp input f4 per tile (3/lane)
#define W_ROWS 64
#define W_OUT_FLOATS (W_ROWS * 9)        // 576

__device__ __forceinline__ void cp_async16(uint32_t saddr, const void* gaddr) {
    asm volatile("cp.async.cg.shared.global [%0], [%1], 16;\n" :: "r"(saddr), "l"(gaddr));
}
__device__ __forceinline__ void cp_commit() {
    asm volatile("cp.async.commit_group;\n" ::: "memory");
}
template <int N>
__device__ __forceinline__ void cp_wait() {
    asm volatile("cp.async.wait_group %0;\n" :: "n"(N) : "memory");
}

__device__ __forceinline__ void bulk_store_hint(void* gaddr, uint32_t saddr, uint32_t bytes) {
    asm volatile(
        "{\n\t.reg .b64 pol;\n\t"
        "createpolicy.fractional.L2::evict_first.b64 pol, 1.0;\n\t"
        "cp.async.bulk.global.shared::cta.bulk_group.L2::cache_hint [%0], [%1], %2, pol;\n\t}"
        :: "l"(gaddr), "r"(saddr), "r"(bytes) : "memory");
}
__device__ __forceinline__ void bulk_commit() {
    asm volatile("cp.async.bulk.commit_group;\n" ::: "memory");
}
template <int N>
__device__ __forceinline__ void bulk_wait() {
    asm volatile("cp.async.bulk.wait_group %0;\n" :: "n"(N) : "memory");
}
__device__ __forceinline__ void fence_async_shared() {
    asm volatile("fence.proxy.async.shared::cta;\n" ::: "memory");
}

__device__ __forceinline__ void row_to_q(const float* __restrict__ v, float* __restrict__ o) {
    const float a = v[0], b = v[1], c = v[2], d = v[3], e = v[4], f = v[5];
    const float ab = a * b;
    const float ad = a * d;
    const float bdce = fmaf(b, d, c * e);
    o[0] = a * a;
    o[1] = ab;
    o[2] = ad;
    o[3] = ab;
    o[4] = fmaf(b, b, c * c);
    o[5] = bdce;
    o[6] = ad;
    o[7] = bdce;
    o[8] = fmaf(d, d, fmaf(e, e, f * f));
}

__device__ __forceinline__ void warp_compute(const float* __restrict__ sin_w,
                                             float* __restrict__ sout_w, int l)
{
#pragma unroll
    for (int j = 0; j < 2; j++) {
        const int r = l + 32 * j;
        float v[6], o[9];
#pragma unroll
        for (int k = 0; k < 6; k++) v[k] = sin_w[r * 6 + k];
        row_to_q(v, o);
#pragma unroll
        for (int k = 0; k < 9; k++) sout_w[r * 9 + k] = o[k];
    }
}

__global__ __launch_bounds__(TPB) void chol_to_cov_pp4(const float4* __restrict__ in4,
                                                       float* __restrict__ out,
                                                       int num_tiles)
{
    __shared__ alignas(16) float s_in[2][TILE_IN_FLOATS];             // 12 KB
    __shared__ alignas(16) float s_out[TILES_PB * TILE_OUT_FLOATS];   // 36 KB

    const int t = threadIdx.x;
    const int w = t >> 5;
    const int l = t & 31;

    const int tile0 = blockIdx.x * TILES_PB;
    const int nt = (num_tiles - tile0 < TILES_PB) ? (num_tiles - tile0) : TILES_PB;

    // Per-warp input slice issue helper (3 x 16B per lane, own commit group).
    auto issue_tile = [&](int i, int buf) {
        if (i < nt) {
            const float4* ip = in4 + (size_t)(tile0 + i) * (TILE_IN_FLOATS / 4) + w * W_IN_F4;
            uint32_t sb = (uint32_t)__cvta_generic_to_shared(&s_in[buf][w * W_IN_F4 * 4]);
#pragma unroll
            for (int k = 0; k < 3; k++)
                cp_async16(sb + (l + 32 * k) * 16u, ip + l + 32 * k);
        }
        cp_commit();
    };

    // Prologue: tiles 0,1 into buffers 0,1.
    issue_tile(0, 0);
    issue_tile(1, 1);

#pragma unroll
    for (int i = 0; i < TILES_PB; i++) {
        const int buf = i & 1;
        if (i < nt) {
            if (i < TILES_PB - 1) cp_wait<1>(); else cp_wait<0>();
            __syncwarp();   // warp's slice of buf fully arrived
            warp_compute(&s_in[buf][w * W_ROWS * 6],
                         &s_out[i * TILE_OUT_FLOATS + w * W_OUT_FLOATS], l);
            __syncwarp();   // all lanes done reading buf before refill
        } else {
            if (i < TILES_PB - 1) cp_wait<1>(); else cp_wait<0>();
        }
        if (i + 2 < TILES_PB) issue_tile(i + 2, buf);  // refill this buffer
    }

    // One large sequential bulk store for the whole block output.
    fence_async_shared();
    __syncthreads();
    if (t == 0) {
        bulk_store_hint(out + (size_t)tile0 * TILE_OUT_FLOATS,
                        (uint32_t)__cvta_generic_to_shared(&s_out[0]),
                        (uint32_t)nt * TILE_OUT_FLOATS * 4u);
        bulk_commit();
        bulk_wait<0>();  // keep smem alive until the bulk engine has read it
    }
}

// Scalar tail for the (< ROWS_PB) remainder rows.
__global__ void chol_to_cov_tail(const float* __restrict__ in,
                                 float* __restrict__ out,
                                 int start_row, int n_rows)
{
    const int r = start_row + blockIdx.x * blockDim.x + threadIdx.x;
    if (r >= n_rows) return;
    float v[6], o[9];
#pragma unroll
    for (int k = 0; k < 6; k++) v[k] = in[(size_t)r * 6 + k];
    row_to_q(v, o);
#pragma unroll
    for (int k = 0; k < 9; k++) out[(size_t)r * 9 + k] = o[k];
}

extern "C" void kernel_launch(void* const* d_in, const int* in_sizes, int n_in,
                              void* d_out, int out_size)
{
    const float* in = (const float*)d_in[0];
    float* out = (float*)d_out;
    const int n_rows = in_sizes[0] / 6;

    const int num_tiles = n_rows / ROWS_PB;
    if (num_tiles > 0) {
        const int blocks = (num_tiles + TILES_PB - 1) / TILES_PB;
        chol_to_cov_pp4<<<blocks, TPB>>>((const float4*)in, out, num_tiles);
    }
    const int done = num_tiles * ROWS_PB;
    if (done < n_rows) {
        const int rem = n_rows - done;
        chol_to_cov_tail<<<(rem + 127) / 128, 128>>>(in, out, done, n_rows);
    }
}

// round 13
// speedup vs baseline: 1.0070x; 1.0070x over previous
#include <cuda_runtime.h>
#include <cstdint>

// Q = L @ L^T, L lower-triangular 3x3 from packed [a,b,c,d,e,f]:
//   Q00=a*a  Q01=a*b      Q02=a*d
//   Q10=a*b  Q11=b*b+c*c  Q12=b*d+c*e
//   Q20=a*d  Q21=b*d+c*e  Q22=d*d+e*e+f*f
//
// Champion (R9) structure with EARLY PER-TILE BULK STORES:
// - Reads: per-lane cp.async.cg, BOTH tiles front-batched (groups 0,1) —
//   the read shape that produced the best DRAM% across all rounds.
// - Writes: one 9216B block-wide cp.async.bulk per tile, issued immediately
//   after that tile's compute. Tile0's writeback overlaps tile1's compute,
//   removing the silent-write prefix and shrinking the end-of-block store
//   tail, while each op remains a large strictly-sequential burst.

#define TPB 128
#define ROWS_PB 256
#define IN_F4 (ROWS_PB * 6 / 4)        // 384 f4/tile ; per warp: 96 (3/lane)
#define TILE_OUT_FLOATS (ROWS_PB * 9)  // 2304 floats = 9216 B
#define W_IN 96
#define W_ROWS 64
#define W_OUT_FLOATS (W_ROWS * 9)      // 576 floats

__device__ __forceinline__ void cp_async16(uint32_t saddr, const void* gaddr) {
    asm volatile("cp.async.cg.shared.global [%0], [%1], 16;\n" :: "r"(saddr), "l"(gaddr));
}
__device__ __forceinline__ void cp_commit() {
    asm volatile("cp.async.commit_group;\n" ::: "memory");
}
template <int N>
__device__ __forceinline__ void cp_wait() {
    asm volatile("cp.async.wait_group %0;\n" :: "n"(N) : "memory");
}

__device__ __forceinline__ void bulk_store(void* gaddr, uint32_t saddr, uint32_t bytes) {
    asm volatile("cp.async.bulk.global.shared::cta.bulk_group [%0], [%1], %2;\n"
                 :: "l"(gaddr), "r"(saddr), "r"(bytes) : "memory");
}
__device__ __forceinline__ void bulk_commit() {
    asm volatile("cp.async.bulk.commit_group;\n" ::: "memory");
}
template <int N>
__device__ __forceinline__ void bulk_wait() {
    asm volatile("cp.async.bulk.wait_group %0;\n" :: "n"(N) : "memory");
}
__device__ __forceinline__ void fence_async_shared() {
    asm volatile("fence.proxy.async.shared::cta;\n" ::: "memory");
}

__device__ __forceinline__ void row_to_q(const float* __restrict__ v, float* __restrict__ o) {
    const float a = v[0], b = v[1], c = v[2], d = v[3], e = v[4], f = v[5];
    const float ab = a * b;
    const float ad = a * d;
    const float bdce = fmaf(b, d, c * e);
    o[0] = a * a;
    o[1] = ab;
    o[2] = ad;
    o[3] = ab;
    o[4] = fmaf(b, b, c * c);
    o[5] = bdce;
    o[6] = ad;
    o[7] = bdce;
    o[8] = fmaf(d, d, fmaf(e, e, f * f));
}

// Compute this warp's 64 rows of one tile: smem input slice -> smem output slice.
__device__ __forceinline__ void warp_compute(const float* __restrict__ sin_w,
                                             float* __restrict__ sout_w, int l)
{
#pragma unroll
    for (int j = 0; j < 2; j++) {
        const int r = l + 32 * j;
        float v[6], o[9];
#pragma unroll
        for (int k = 0; k < 6; k++) v[k] = sin_w[r * 6 + k];
        row_to_q(v, o);
#pragma unroll
        for (int k = 0; k < 9; k++) sout_w[r * 9 + k] = o[k];
    }
}

__global__ __launch_bounds__(TPB) void chol_to_cov_early(const float4* __restrict__ in4,
                                                         float* __restrict__ out,
                                                         int num_tiles)
{
    __shared__ float4 s_in[2][IN_F4];              // 12 KB
    __shared__ float  s_out[2 * TILE_OUT_FLOATS];  // 18 KB

    const int t = threadIdx.x;
    const int w = t >> 5;
    const int l = t & 31;

    const int tile0 = blockIdx.x * 2;
    const int tile1 = tile0 + 1;
    const bool has1 = (tile1 < num_tiles);

    // Front-batch BOTH tiles' input slices: tile0 -> group0, tile1 -> group1.
    {
        const float4* ip0 = in4 + (size_t)tile0 * IN_F4 + w * W_IN;
        uint32_t sb0 = (uint32_t)__cvta_generic_to_shared(&s_in[0][w * W_IN]);
#pragma unroll
        for (int k = 0; k < 3; k++)
            cp_async16(sb0 + (l + 32 * k) * 16u, ip0 + l + 32 * k);
        cp_commit();
        if (has1) {
            const float4* ip1 = in4 + (size_t)tile1 * IN_F4 + w * W_IN;
            uint32_t sb1 = (uint32_t)__cvta_generic_to_shared(&s_in[1][w * W_IN]);
#pragma unroll
            for (int k = 0; k < 3; k++)
                cp_async16(sb1 + (l + 32 * k) * 16u, ip1 + l + 32 * k);
            cp_commit();
        }
    }

    // ---- Tile 0: compute, then issue its 9KB bulk store immediately ----
    if (has1) cp_wait<1>(); else cp_wait<0>();
    __syncwarp();
    warp_compute(reinterpret_cast<const float*>(&s_in[0][w * W_IN]),
                 &s_out[w * W_OUT_FLOATS], l);
    fence_async_shared();
    __syncthreads();                 // all warps' tile0 output in smem
    if (t == 0) {
        bulk_store(out + (size_t)tile0 * TILE_OUT_FLOATS,
                   (uint32_t)__cvta_generic_to_shared(&s_out[0]),
                   TILE_OUT_FLOATS * 4u);
        bulk_commit();
    }

    // ---- Tile 1: compute (overlaps tile0 writeback), then store ----
    if (has1) {
        cp_wait<0>();
        __syncwarp();
        warp_compute(reinterpret_cast<const float*>(&s_in[1][w * W_IN]),
                     &s_out[TILE_OUT_FLOATS + w * W_OUT_FLOATS], l);
        fence_async_shared();
        __syncthreads();
        if (t == 0) {
            bulk_store(out + (size_t)tile1 * TILE_OUT_FLOATS,
                       (uint32_t)__cvta_generic_to_shared(&s_out[TILE_OUT_FLOATS]),
                       TILE_OUT_FLOATS * 4u);
            bulk_commit();
        }
    }

    // Keep smem alive until the bulk engine has read both tiles.
    if (t == 0) bulk_wait<0>();
}

// Scalar tail for the (< ROWS_PB) remainder rows.
__global__ void chol_to_cov_tail(const float* __restrict__ in,
                                 float* __restrict__ out,
                                 int start_row, int n_rows)
{
    const int r = start_row + blockIdx.x * blockDim.x + threadIdx.x;
    if (r >= n_rows) return;
    float v[6], o[9];
#pragma unroll
    for (int k = 0; k < 6; k++) v[k] = in[(size_t)r * 6 + k];
    row_to_q(v, o);
#pragma unroll
    for (int k = 0; k < 9; k++) out[(size_t)r * 9 + k] = o[k];
}

extern "C" void kernel_launch(void* const* d_in, const int* in_sizes, int n_in,
                              void* d_out, int out_size)
{
    const float* in = (const float*)d_in[0];
    float* out = (float*)d_out;
    const int n_rows = in_sizes[0] / 6;

    const int num_tiles = n_rows / ROWS_PB;
    if (num_tiles > 0) {
        const int blocks = (num_tiles + 1) / 2;
        chol_to_cov_early<<<blocks, TPB>>>((const float4*)in, out, num_tiles);
    }
    const int done = num_tiles * ROWS_PB;
    if (done < n_rows) {
        const int rem = n_rows - done;
        chol_to_cov_tail<<<(rem + 127) / 128, 128>>>(in, out, done, n_rows);
    }
}

// round 14
// speedup vs baseline: 1.0195x; 1.0125x over previous
#include <cuda_runtime.h>
#include <cstdint>

// Q = L @ L^T, L lower-triangular 3x3 from packed [a,b,c,d,e,f]:
//   Q00=a*a  Q01=a*b      Q02=a*d
//   Q10=a*b  Q11=b*b+c*c  Q12=b*d+c*e
//   Q20=a*d  Q21=b*d+c*e  Q22=d*d+e*e+f*f
//
// Champion structure (R9): 2 tiles/block, per-lane cp.async.cg reads
// front-batched for BOTH tiles, warp-autonomous compute, and ONE 18KB
// contiguous cp.async.bulk store at block end.
// R14 delta: L2::cache_hint evict_first on BOTH streams — input is
// read-once, output write-once, so neither should occupy L2; prompt
// eviction leaves L2 free to buffer the opposing stream.

#define TPB 128
#define ROWS_PB 256
#define IN_F4 (ROWS_PB * 6 / 4)        // 384 f4/tile ; per warp: 96 (3/lane)
#define TILE_OUT_FLOATS (ROWS_PB * 9)  // 2304 floats = 9216 B
#define W_IN 96
#define W_ROWS 64
#define W_OUT_FLOATS (W_ROWS * 9)      // 576 floats

__device__ __forceinline__ uint64_t evict_first_policy() {
    uint64_t pol;
    asm volatile("createpolicy.fractional.L2::evict_first.b64 %0, 1.0;\n" : "=l"(pol));
    return pol;
}

__device__ __forceinline__ void cp_async16_hint(uint32_t saddr, const void* gaddr, uint64_t pol) {
    asm volatile("cp.async.cg.shared.global.L2::cache_hint [%0], [%1], 16, %2;\n"
                 :: "r"(saddr), "l"(gaddr), "l"(pol));
}
__device__ __forceinline__ void cp_commit() {
    asm volatile("cp.async.commit_group;\n" ::: "memory");
}
template <int N>
__device__ __forceinline__ void cp_wait() {
    asm volatile("cp.async.wait_group %0;\n" :: "n"(N) : "memory");
}

__device__ __forceinline__ void bulk_store_hint(void* gaddr, uint32_t saddr,
                                                uint32_t bytes, uint64_t pol) {
    asm volatile(
        "cp.async.bulk.global.shared::cta.bulk_group.L2::cache_hint [%0], [%1], %2, %3;\n"
        :: "l"(gaddr), "r"(saddr), "r"(bytes), "l"(pol) : "memory");
}
__device__ __forceinline__ void bulk_commit() {
    asm volatile("cp.async.bulk.commit_group;\n" ::: "memory");
}
template <int N>
__device__ __forceinline__ void bulk_wait() {
    asm volatile("cp.async.bulk.wait_group %0;\n" :: "n"(N) : "memory");
}
__device__ __forceinline__ void fence_async_shared() {
    asm volatile("fence.proxy.async.shared::cta;\n" ::: "memory");
}

__device__ __forceinline__ void row_to_q(const float* __restrict__ v, float* __restrict__ o) {
    const float a = v[0], b = v[1], c = v[2], d = v[3], e = v[4], f = v[5];
    const float ab = a * b;
    const float ad = a * d;
    const float bdce = fmaf(b, d, c * e);
    o[0] = a * a;
    o[1] = ab;
    o[2] = ad;
    o[3] = ab;
    o[4] = fmaf(b, b, c * c);
    o[5] = bdce;
    o[6] = ad;
    o[7] = bdce;
    o[8] = fmaf(d, d, fmaf(e, e, f * f));
}

// Compute this warp's 64 rows of one tile: smem input slice -> smem output slice.
__device__ __forceinline__ void warp_compute(const float* __restrict__ sin_w,
                                             float* __restrict__ sout_w, int l)
{
#pragma unroll
    for (int j = 0; j < 2; j++) {
        const int r = l + 32 * j;
        float v[6], o[9];
#pragma unroll
        for (int k = 0; k < 6; k++) v[k] = sin_w[r * 6 + k];
        row_to_q(v, o);
#pragma unroll
        for (int k = 0; k < 9; k++) sout_w[r * 9 + k] = o[k];
    }
}

__global__ __launch_bounds__(TPB) void chol_to_cov_r14(const float4* __restrict__ in4,
                                                       float* __restrict__ out,
                                                       int num_tiles)
{
    __shared__ float4 s_in[2][IN_F4];              // 12 KB
    __shared__ float  s_out[2 * TILE_OUT_FLOATS];  // 18 KB, contiguous both tiles

    const int t = threadIdx.x;
    const int w = t >> 5;
    const int l = t & 31;

    const int tile0 = blockIdx.x * 2;
    const int tile1 = tile0 + 1;
    const bool has1 = (tile1 < num_tiles);

    const uint64_t pol = evict_first_policy();

    // Front-batch BOTH tiles' input slices: tile0 -> group0, tile1 -> group1.
    {
        const float4* ip0 = in4 + (size_t)tile0 * IN_F4 + w * W_IN;
        uint32_t sb0 = (uint32_t)__cvta_generic_to_shared(&s_in[0][w * W_IN]);
#pragma unroll
        for (int k = 0; k < 3; k++)
            cp_async16_hint(sb0 + (l + 32 * k) * 16u, ip0 + l + 32 * k, pol);
        cp_commit();
        if (has1) {
            const float4* ip1 = in4 + (size_t)tile1 * IN_F4 + w * W_IN;
            uint32_t sb1 = (uint32_t)__cvta_generic_to_shared(&s_in[1][w * W_IN]);
#pragma unroll
            for (int k = 0; k < 3; k++)
                cp_async16_hint(sb1 + (l + 32 * k) * 16u, ip1 + l + 32 * k, pol);
            cp_commit();
        }
    }

    // ---- Tile 0 compute ----
    if (has1) cp_wait<1>(); else cp_wait<0>();
    __syncwarp();
    warp_compute(reinterpret_cast<const float*>(&s_in[0][w * W_IN]),
                 &s_out[w * W_OUT_FLOATS], l);

    // ---- Tile 1 compute ----
    if (has1) {
        cp_wait<0>();
        __syncwarp();
        warp_compute(reinterpret_cast<const float*>(&s_in[1][w * W_IN]),
                     &s_out[TILE_OUT_FLOATS + w * W_OUT_FLOATS], l);
    }

    // One large sequential bulk store for the whole block output.
    fence_async_shared();
    __syncthreads();
    if (t == 0) {
        const uint32_t bytes = has1 ? 2 * TILE_OUT_FLOATS * 4 : TILE_OUT_FLOATS * 4;
        bulk_store_hint(out + (size_t)tile0 * TILE_OUT_FLOATS,
                        (uint32_t)__cvta_generic_to_shared(&s_out[0]), bytes, pol);
        bulk_commit();
        bulk_wait<0>();  // keep smem alive until the bulk engine has read it
    }
}

// Scalar tail for the (< ROWS_PB) remainder rows.
__global__ void chol_to_cov_tail(const float* __restrict__ in,
                                 float* __restrict__ out,
                                 int start_row, int n_rows)
{
    const int r = start_row + blockIdx.x * blockDim.x + threadIdx.x;
    if (r >= n_rows) return;
    float v[6], o[9];
#pragma unroll
    for (int k = 0; k < 6; k++) v[k] = in[(size_t)r * 6 + k];
    row_to_q(v, o);
#pragma unroll
    for (int k = 0; k < 9; k++) out[(size_t)r * 9 + k] = o[k];
}

extern "C" void kernel_launch(void* const* d_in, const int* in_sizes, int n_in,
                              void* d_out, int out_size)
{
    const float* in = (const float*)d_in[0];
    float* out = (float*)d_out;
    const int n_rows = in_sizes[0] / 6;

    const int num_tiles = n_rows / ROWS_PB;
    if (num_tiles > 0) {
        const int blocks = (num_tiles + 1) / 2;
        chol_to_cov_r14<<<blocks, TPB>>>((const float4*)in, out, num_tiles);
    }
    const int done = num_tiles * ROWS_PB;
    if (done < n_rows) {
        const int rem = n_rows - done;
        chol_to_cov_tail<<<(rem + 127) / 128, 128>>>(in, out, done, n_rows);
    }
}